// round 9
// baseline (speedup 1.0000x reference)
#include <cuda_runtime.h>
#include <cstdint>

// ---------------------------------------------------------------------------
// LSTM Neural Hawkes Process NLL  (B=64, L=1024, H=64)
// R9: single 512-thread CTA per batch.
//   warps 0-11  : GEMM producers (gates 0..5); warp 11 also generates the
//                 threefry uniforms (2 sites ahead) in its bar2 wait window.
//   warps 12-13 : gate-6 columns + epilogue; stage MC params in smem ping-pong.
//   warps 14-15 : MC consumers (15 samples each) fed purely through smem,
//                 synchronized by the existing bar2. Zero gmem state traffic.
// Final NLL reduced in-kernel via last-CTA pattern. ONE launch.
// ---------------------------------------------------------------------------

#define BATCH   64
#define MAXL    1024
#define LP1     1025
#define HID     64
#define NCOL    448
#define NTHR    512
#define NMC     30
#define T_END   100.0f
#define EPS_L   1e-10f
#define TOTAL   (BATCH * LP1)          // 65600
#define LOG2E   1.4426950408889634f
#define LN2     0.6931471805599453f

// ------------------------- device scratch (no mallocs) ---------------------
__device__ float    g_part[BATCH];
__device__ unsigned g_done = 0;

// ------------------------------ fast math -----------------------------------
__device__ __forceinline__ float ex2f(float x){ float y; asm("ex2.approx.f32 %0,%1;":"=f"(y):"f"(x)); return y; }
__device__ __forceinline__ float lg2f(float x){ float y; asm("lg2.approx.f32 %0,%1;":"=f"(y):"f"(x)); return y; }
__device__ __forceinline__ float tanh_mufu(float x){ float y; asm("tanh.approx.f32 %0,%1;":"=f"(y):"f"(x)); return y; }
__device__ __forceinline__ float fsoftplus(float x){
    return fmaxf(x, 0.0f) + LN2 * lg2f(1.0f + ex2f(-fabsf(x) * LOG2E));
}
__device__ __forceinline__ float flog(float x){ return LN2 * lg2f(x); }

// ------------------------------ packed f32x2 --------------------------------
__device__ __forceinline__ void fma2(unsigned long long& d, unsigned long long a, unsigned long long b){
    asm("fma.rn.f32x2 %0, %1, %2, %0;" : "+l"(d) : "l"(a), "l"(b));
}
__device__ __forceinline__ void add2(unsigned long long& d, unsigned long long a){
    asm("add.rn.f32x2 %0, %1, %0;" : "+l"(d) : "l"(a));
}
__device__ __forceinline__ unsigned long long pack2(float lo, float hi){
    unsigned long long r; asm("mov.b64 %0, {%1,%2};" : "=l"(r) : "f"(lo), "f"(hi)); return r;
}
__device__ __forceinline__ float2 unpack2(unsigned long long v){
    float2 r; asm("mov.b64 {%0,%1}, %2;" : "=f"(r.x), "=f"(r.y) : "l"(v)); return r;
}

// ------------------------------ named barriers ------------------------------
// bar1 (count 448): producers arrive, epilogue syncs   (gates ready)
// bar2 (count 512): producers+MC sync, epilogue arrives (h + staging ready)
#define BAR1_ARRIVE() asm volatile("bar.arrive 1, 448;" ::: "memory")
#define BAR1_SYNC()   asm volatile("bar.sync   1, 448;" ::: "memory")
#define BAR2_ARRIVE() asm volatile("bar.arrive 2, 512;" ::: "memory")
#define BAR2_SYNC()   asm volatile("bar.sync   2, 512;" ::: "memory")

// ------------------------------ Threefry-2x32-20 ----------------------------
__device__ __forceinline__ uint32_t rotl32(uint32_t x, int r){ return (x << r) | (x >> (32 - r)); }
__device__ __forceinline__ float tf_uniform(uint32_t flat){
    // JAX partitionable threefry, key (0,42): bits = out0 ^ out1
    uint32_t k0 = 0u, k1 = 42u, ks2 = k0 ^ k1 ^ 0x1BD11BDAu;
    uint32_t x0 = 0u + k0, x1 = flat + k1;
#define TF_R(r) { x0 += x1; x1 = rotl32(x1, (r)); x1 ^= x0; }
    TF_R(13) TF_R(15) TF_R(26) TF_R(6)   x0 += k1;  x1 += ks2 + 1u;
    TF_R(17) TF_R(29) TF_R(16) TF_R(24)  x0 += ks2; x1 += k0  + 2u;
    TF_R(13) TF_R(15) TF_R(26) TF_R(6)   x0 += k0;  x1 += k1  + 3u;
    TF_R(17) TF_R(29) TF_R(16) TF_R(24)  x0 += k1;  x1 += ks2 + 4u;
    TF_R(13) TF_R(15) TF_R(26) TF_R(6)   x0 += ks2; x1 += k0  + 5u;
#undef TF_R
    uint32_t bits = x0 ^ x1;
    return __uint_as_float((bits >> 9) | 0x3F800000u) - 1.0f;
}

// 65-long packed-f32x2 column dot against shared h
__device__ __forceinline__ float col_dot(const float* sh, const unsigned long long* w2,
                                         float w0, float bj, float dt)
{
    unsigned long long a0 = 0ull, a1 = 0ull, a2 = 0ull, a3 = 0ull;
    const ulonglong2* h2 = reinterpret_cast<const ulonglong2*>(sh);
#pragma unroll
    for (int q = 0; q < 4; q++) {
        ulonglong2 u = h2[2*q], v = h2[2*q + 1];
        fma2(a0, w2[4*q + 0],  u.x);
        fma2(a1, w2[4*q + 1],  u.y);
        fma2(a2, w2[4*q + 2],  v.x);
        fma2(a3, w2[4*q + 3],  v.y);
        ulonglong2 s = h2[2*q + 8], t = h2[2*q + 9];
        fma2(a0, w2[4*q + 16], s.x);
        fma2(a1, w2[4*q + 17], s.y);
        fma2(a2, w2[4*q + 18], t.x);
        fma2(a3, w2[4*q + 19], t.y);
    }
    add2(a0, a1); add2(a2, a3); add2(a0, a2);
    float2 r = unpack2(a0);
    return (r.x + r.y) + fmaf(w0, dt, bj);
}

// ------------------------------- main kernel ---------------------------------
__global__ void __launch_bounds__(NTHR, 1)
hawkes_kernel(const float* __restrict__ seq,    // [B, L, 1]
              const float* __restrict__ Wrec,   // [65, 448]
              const float* __restrict__ brec,   // [448]
              const float* __restrict__ Wf,     // [64]
              const float* __restrict__ bf,     // [1]
              const int*   __restrict__ lens,   // [B]
              float*       __restrict__ out)
{
    __shared__ __align__(16) float  s_h[HID];
    __shared__ float  s_v[384];                    // gates 0..5
    __shared__ float  s_dt[LP1];
    __shared__ __align__(16) float4 s_mc[2][HID];  // {m, A, cbar, o*wf} per site
    __shared__ float  s_bw[2][HID];                // before*wf per site
    __shared__ float  s_u[4][32];                  // uniform ring, site & 3
    __shared__ float  s_red[8];

    const int b    = blockIdx.x;
    const int j    = threadIdx.x;
    const int w    = j >> 5;
    const int lane = j & 31;
    const int len  = lens[b];
    const float bfv = bf[0];
    const float* sp = seq + b * MAXL;

    for (int l = j; l <= MAXL; l += NTHR) {
        float v;
        if (l < len)        v = (l == 0) ? sp[0] : sp[l] - sp[l - 1];
        else if (l == len)  v = T_END - sp[len - 1];
        else                v = -1.0f;
        s_dt[l] = v;
    }

    // site-0 staging = zero state; h init
    if (j >= 384 && j < 448) {
        const int ch = j - 384;
        s_h[ch] = 0.0f;
        s_mc[0][ch] = make_float4(0.f, 0.f, 0.f, 0.f);
        s_bw[0][ch] = 0.0f;
    }
    // prefill uniforms for sites 0, 1 (warps 10, 11)
    if (w == 10 && lane < NMC)
        s_u[0][lane] = tf_uniform((uint32_t)lane * TOTAL + (uint32_t)(b * LP1));
    if (w == 11 && lane < NMC)
        s_u[1][lane] = tf_uniform((uint32_t)lane * TOTAL + (uint32_t)(b * LP1 + 1));

    // column weights (scan threads only)
    float w0 = 0.f, bj = 0.f;
    unsigned long long w2[32];
    if (j < NCOL) {
        w0 = Wrec[j];
        bj = brec[j];
#pragma unroll
        for (int k = 0; k < 32; k++)
            w2[k] = pack2(Wrec[(2*k + 1) * NCOL + j], Wrec[(2*k + 2) * NCOL + j]);
    }

    __syncthreads();

    if (j < 384) {
        // =============== producers: warps 0-11 (gates 0..5) ================
        const int  gate = j >> 6;
        const float al = (gate == 2) ? 1.0f : 0.5f;
        const float be = (gate == 2) ? 1.0f : 0.5f;
        const float ga = (gate == 2) ? 0.0f : 0.5f;
        const bool rng = (w == 11) && (lane < NMC);

        for (int l = 0; l < len; l++) {
            const float acc = col_dot(s_h, w2, w0, bj, s_dt[l]);
            s_v[j] = fmaf(al, tanh_mufu(be * acc), ga);
            BAR1_ARRIVE();
            // warp 11: uniforms for site l+2 inside the bar2 wait window
            if (rng && (l + 2) <= len)
                s_u[(l + 2) & 3][lane] =
                    tf_uniform((uint32_t)lane * TOTAL + (uint32_t)(b * LP1 + l + 2));
            BAR2_SYNC();
        }
    } else if (j < 448) {
        // ============ epilogue: warps 12,13 (= gate-6 columns) =============
        const int ch = j - 384;
        const float wfc = Wf[ch];
        float ct = 0.0f, cbar = 0.0f;

        for (int l = 0; l < len; l++) {
            const float acc = col_dot(s_h, w2, w0, bj, s_dt[l]);
            const float dec = fsoftplus(acc);
            const float me  = -dec * s_dt[l + 1] * LOG2E;
            const float e   = ex2f(me);

            BAR1_SYNC();
            const float iG = s_v[ch],        fG = s_v[ 64 + ch];
            const float zG = s_v[128 + ch],  oG = s_v[192 + ch];
            const float ib = s_v[256 + ch],  fb = s_v[320 + ch];
            const float c  = fmaf(fG, ct, iG * zG);
            const float cb = fmaf(fb, cbar, ib * zG);
            const float cd = fmaf(c - cb, e, cb);
            const float bef = oG * tanh_mufu(cd);
            ct = cd; cbar = cb;
            s_h[ch] = bef;
            const int p = (l + 1) & 1;                 // stage site l+1
            s_mc[p][ch] = make_float4(me, c - cb, cb, oG * wfc);
            s_bw[p][ch] = bef * wfc;
            BAR2_ARRIVE();
        }
    } else {
        // =============== MC consumers: warps 14,15 =========================
        const int mw = w - 14;                          // 0 or 1
        const int k0 = mw * 15;                         // samples [k0, k0+15)
        float accW = 0.f, accEv = 0.f, accDt = 0.f;

        for (int s = 0; s <= len; s++) {
            if (s > 0) BAR2_SYNC();                     // site s staged
            const float dtl = s_dt[s];
            const float4 t0 = s_mc[s & 1][lane];
            const float4 t1 = s_mc[s & 1][lane + 32];
            const float* us = s_u[s & 3];
            float acc = 0.f;
#pragma unroll 5
            for (int k = 0; k < 15; k++) {
                const float uk = us[k0 + k];
                const float h0 = t0.w * tanh_mufu(fmaf(t0.y, ex2f(uk * t0.x), t0.z));
                const float h1 = t1.w * tanh_mufu(fmaf(t1.y, ex2f(uk * t1.x), t1.z));
                float p = h0 + h1;
#pragma unroll
                for (int off = 16; off; off >>= 1)
                    p += __shfl_xor_sync(0xFFFFFFFFu, p, off);
                acc += fsoftplus(p + bfv);
            }
            accW = fmaf(acc, dtl, accW);
            if (mw == 0) {
                accDt += dtl;
                if (s < len) {                          // event log-term
                    float q = s_bw[s & 1][lane] + s_bw[s & 1][lane + 32];
#pragma unroll
                    for (int off = 16; off; off >>= 1)
                        q += __shfl_xor_sync(0xFFFFFFFFu, q, off);
                    accEv += flog(fsoftplus(q + bfv) + EPS_L);
                }
            }
        }
        if (lane == 0) {
            s_red[mw * 3 + 0] = accW;
            s_red[mw * 3 + 1] = accEv;
            s_red[mw * 3 + 2] = accDt;
        }
    }

    __syncthreads();
    if (j == 0) {
        const float SW = s_red[0] + s_red[3];
        g_part[b] = s_red[1] - (SW * (1.0f / NMC) + EPS_L * s_red[2]);
        __threadfence();
        if (atomicAdd(&g_done, 1u) == BATCH - 1) {      // last CTA reduces
            float S = 0.0f;
#pragma unroll 8
            for (int k = 0; k < BATCH; k++) S += g_part[k];
            out[0] = -S * (1.0f / BATCH);
            g_done = 0u;                                // reset for replays
        }
    }
}

// ------------------------------- launcher ------------------------------------
extern "C" void kernel_launch(void* const* d_in, const int* in_sizes, int n_in,
                              void* d_out, int out_size)
{
    const float* seq  = nullptr;
    const float* Wrec = nullptr;
    const float* brec = nullptr;
    const float* Wf   = nullptr;
    const float* bf   = nullptr;
    const int*   lens = nullptr;
    for (int i = 0; i < n_in; i++) {
        const int s = in_sizes[i];
        if      (s == BATCH * MAXL)     seq  = (const float*)d_in[i];
        else if (s == 65 * NCOL)        Wrec = (const float*)d_in[i];
        else if (s == NCOL)             brec = (const float*)d_in[i];
        else if (s == 1)                bf   = (const float*)d_in[i];
        else if (s == HID) {
            if (!Wf) Wf = (const float*)d_in[i];
            else     lens = (const int*)d_in[i];
        }
    }

    hawkes_kernel<<<BATCH, NTHR>>>(seq, Wrec, brec, Wf, bf, lens, (float*)d_out);
}

// round 10
// speedup vs baseline: 1.5904x; 1.5904x over previous
#include <cuda_runtime.h>
#include <cstdint>

// ---------------------------------------------------------------------------
// LSTM Neural Hawkes Process NLL  (B=64, L=1024, H=64)
// R10: single 512-thread CTA per batch (R9 fabric, fixed MC pacing).
//   warps 0-11  : GEMM producers; warp 11 threefry-prefetches uniforms.
//   warps 12-13 : gate-6 columns + epilogue; stage MC params in smem ping-pong.
//   warps 14-15 : MC consumers, LANE = SAMPLE layout (no in-loop shuffles);
//                 channels split 0-31 / 32-63, combined via bar3(64).
// One launch; last-CTA in-kernel reduction.
// ---------------------------------------------------------------------------

#define BATCH   64
#define MAXL    1024
#define LP1     1025
#define HID     64
#define NCOL    448
#define NTHR    512
#define NMC     30
#define T_END   100.0f
#define EPS_L   1e-10f
#define TOTAL   (BATCH * LP1)          // 65600
#define LOG2E   1.4426950408889634f
#define LN2     0.6931471805599453f

// ------------------------- device scratch (no mallocs) ---------------------
__device__ float    g_part[BATCH];
__device__ unsigned g_done = 0;

// ------------------------------ fast math -----------------------------------
__device__ __forceinline__ float ex2f(float x){ float y; asm("ex2.approx.f32 %0,%1;":"=f"(y):"f"(x)); return y; }
__device__ __forceinline__ float lg2f(float x){ float y; asm("lg2.approx.f32 %0,%1;":"=f"(y):"f"(x)); return y; }
__device__ __forceinline__ float tanh_mufu(float x){ float y; asm("tanh.approx.f32 %0,%1;":"=f"(y):"f"(x)); return y; }
__device__ __forceinline__ float fsoftplus(float x){
    return fmaxf(x, 0.0f) + LN2 * lg2f(1.0f + ex2f(-fabsf(x) * LOG2E));
}
__device__ __forceinline__ float flog(float x){ return LN2 * lg2f(x); }

// ------------------------------ packed f32x2 --------------------------------
__device__ __forceinline__ void fma2(unsigned long long& d, unsigned long long a, unsigned long long b){
    asm("fma.rn.f32x2 %0, %1, %2, %0;" : "+l"(d) : "l"(a), "l"(b));
}
__device__ __forceinline__ void add2(unsigned long long& d, unsigned long long a){
    asm("add.rn.f32x2 %0, %1, %0;" : "+l"(d) : "l"(a));
}
__device__ __forceinline__ unsigned long long pack2(float lo, float hi){
    unsigned long long r; asm("mov.b64 %0, {%1,%2};" : "=l"(r) : "f"(lo), "f"(hi)); return r;
}
__device__ __forceinline__ float2 unpack2(unsigned long long v){
    float2 r; asm("mov.b64 {%0,%1}, %2;" : "=f"(r.x), "=f"(r.y) : "l"(v)); return r;
}

// ------------------------------ named barriers ------------------------------
// bar1 (448): producers arrive, epilogue syncs    (gates ready)
// bar2 (512): producers+MC sync, epilogue arrives (h + staging ready)
// bar3 (64) : warp15 arrives, warp14 syncs        (channel partial ready)
#define BAR1_ARRIVE() asm volatile("bar.arrive 1, 448;" ::: "memory")
#define BAR1_SYNC()   asm volatile("bar.sync   1, 448;" ::: "memory")
#define BAR2_ARRIVE() asm volatile("bar.arrive 2, 512;" ::: "memory")
#define BAR2_SYNC()   asm volatile("bar.sync   2, 512;" ::: "memory")
#define BAR3_ARRIVE() asm volatile("bar.arrive 3, 64;"  ::: "memory")
#define BAR3_SYNC()   asm volatile("bar.sync   3, 64;"  ::: "memory")

// ------------------------------ Threefry-2x32-20 ----------------------------
__device__ __forceinline__ uint32_t rotl32(uint32_t x, int r){ return (x << r) | (x >> (32 - r)); }
__device__ __forceinline__ float tf_uniform(uint32_t flat){
    // JAX partitionable threefry, key (0,42): bits = out0 ^ out1
    uint32_t k0 = 0u, k1 = 42u, ks2 = k0 ^ k1 ^ 0x1BD11BDAu;
    uint32_t x0 = 0u + k0, x1 = flat + k1;
#define TF_R(r) { x0 += x1; x1 = rotl32(x1, (r)); x1 ^= x0; }
    TF_R(13) TF_R(15) TF_R(26) TF_R(6)   x0 += k1;  x1 += ks2 + 1u;
    TF_R(17) TF_R(29) TF_R(16) TF_R(24)  x0 += ks2; x1 += k0  + 2u;
    TF_R(13) TF_R(15) TF_R(26) TF_R(6)   x0 += k0;  x1 += k1  + 3u;
    TF_R(17) TF_R(29) TF_R(16) TF_R(24)  x0 += k1;  x1 += ks2 + 4u;
    TF_R(13) TF_R(15) TF_R(26) TF_R(6)   x0 += ks2; x1 += k0  + 5u;
#undef TF_R
    uint32_t bits = x0 ^ x1;
    return __uint_as_float((bits >> 9) | 0x3F800000u) - 1.0f;
}

// 65-long packed-f32x2 column dot against shared h
__device__ __forceinline__ float col_dot(const float* sh, const unsigned long long* w2,
                                         float w0, float bj, float dt)
{
    unsigned long long a0 = 0ull, a1 = 0ull, a2 = 0ull, a3 = 0ull;
    const ulonglong2* h2 = reinterpret_cast<const ulonglong2*>(sh);
#pragma unroll
    for (int q = 0; q < 4; q++) {
        ulonglong2 u = h2[2*q], v = h2[2*q + 1];
        fma2(a0, w2[4*q + 0],  u.x);
        fma2(a1, w2[4*q + 1],  u.y);
        fma2(a2, w2[4*q + 2],  v.x);
        fma2(a3, w2[4*q + 3],  v.y);
        ulonglong2 s = h2[2*q + 8], t = h2[2*q + 9];
        fma2(a0, w2[4*q + 16], s.x);
        fma2(a1, w2[4*q + 17], s.y);
        fma2(a2, w2[4*q + 18], t.x);
        fma2(a3, w2[4*q + 19], t.y);
    }
    add2(a0, a1); add2(a2, a3); add2(a0, a2);
    float2 r = unpack2(a0);
    return (r.x + r.y) + fmaf(w0, dt, bj);
}

// ------------------------------- main kernel ---------------------------------
__global__ void __launch_bounds__(NTHR, 1)
hawkes_kernel(const float* __restrict__ seq,    // [B, L, 1]
              const float* __restrict__ Wrec,   // [65, 448]
              const float* __restrict__ brec,   // [448]
              const float* __restrict__ Wf,     // [64]
              const float* __restrict__ bf,     // [1]
              const int*   __restrict__ lens,   // [B]
              float*       __restrict__ out)
{
    __shared__ __align__(16) float  s_h[HID];
    __shared__ float  s_v[384];                    // gates 0..5
    __shared__ float  s_dt[LP1];
    __shared__ __align__(16) float4 s_mc[2][HID];  // {m, A, cbar, o*wf} per site
    __shared__ float  s_bw[2][HID];                // before*wf per site
    __shared__ float  s_u[4][32];                  // uniform ring, site & 3
    __shared__ float  s_pp[2][32];                 // warp15 channel partials
    __shared__ float  s_red[8];

    const int b    = blockIdx.x;
    const int j    = threadIdx.x;
    const int w    = j >> 5;
    const int lane = j & 31;
    const int len  = lens[b];
    const float bfv = bf[0];
    const float* sp = seq + b * MAXL;

    for (int l = j; l <= MAXL; l += NTHR) {
        float v;
        if (l < len)        v = (l == 0) ? sp[0] : sp[l] - sp[l - 1];
        else if (l == len)  v = T_END - sp[len - 1];
        else                v = -1.0f;
        s_dt[l] = v;
    }

    // site-0 staging = zero state; h init
    if (j >= 384 && j < 448) {
        const int ch = j - 384;
        s_h[ch] = 0.0f;
        s_mc[0][ch] = make_float4(0.f, 0.f, 0.f, 0.f);
        s_bw[0][ch] = 0.0f;
    }
    // prefill uniforms for sites 0, 1 (warps 10, 11)
    if (w == 10 && lane < NMC)
        s_u[0][lane] = tf_uniform((uint32_t)lane * TOTAL + (uint32_t)(b * LP1));
    if (w == 11 && lane < NMC)
        s_u[1][lane] = tf_uniform((uint32_t)lane * TOTAL + (uint32_t)(b * LP1 + 1));

    // column weights (scan threads only)
    float w0 = 0.f, bj = 0.f;
    unsigned long long w2[32];
    if (j < NCOL) {
        w0 = Wrec[j];
        bj = brec[j];
#pragma unroll
        for (int k = 0; k < 32; k++)
            w2[k] = pack2(Wrec[(2*k + 1) * NCOL + j], Wrec[(2*k + 2) * NCOL + j]);
    }

    __syncthreads();

    if (j < 384) {
        // =============== producers: warps 0-11 (gates 0..5) ================
        const int  gate = j >> 6;
        const float al = (gate == 2) ? 1.0f : 0.5f;
        const float be = (gate == 2) ? 1.0f : 0.5f;
        const float ga = (gate == 2) ? 0.0f : 0.5f;
        const bool rng = (w == 11) && (lane < NMC);

        for (int l = 0; l < len; l++) {
            const float acc = col_dot(s_h, w2, w0, bj, s_dt[l]);
            s_v[j] = fmaf(al, tanh_mufu(be * acc), ga);
            BAR1_ARRIVE();
            // warp 11: uniforms for site l+2 inside the bar2 wait window
            if (rng && (l + 2) <= len)
                s_u[(l + 2) & 3][lane] =
                    tf_uniform((uint32_t)lane * TOTAL + (uint32_t)(b * LP1 + l + 2));
            BAR2_SYNC();
        }
    } else if (j < 448) {
        // ============ epilogue: warps 12,13 (= gate-6 columns) =============
        const int ch = j - 384;
        const float wfc = Wf[ch];
        float ct = 0.0f, cbar = 0.0f;

        for (int l = 0; l < len; l++) {
            const float acc = col_dot(s_h, w2, w0, bj, s_dt[l]);
            const float dec = fsoftplus(acc);
            const float me  = -dec * s_dt[l + 1] * LOG2E;
            const float e   = ex2f(me);

            BAR1_SYNC();
            const float iG = s_v[ch],        fG = s_v[ 64 + ch];
            const float zG = s_v[128 + ch],  oG = s_v[192 + ch];
            const float ib = s_v[256 + ch],  fb = s_v[320 + ch];
            const float c  = fmaf(fG, ct, iG * zG);
            const float cb = fmaf(fb, cbar, ib * zG);
            const float cd = fmaf(c - cb, e, cb);
            const float bef = oG * tanh_mufu(cd);
            ct = cd; cbar = cb;
            s_h[ch] = bef;
            const int p = (l + 1) & 1;                 // stage site l+1
            s_mc[p][ch] = make_float4(me, c - cb, cb, oG * wfc);
            s_bw[p][ch] = bef * wfc;
            BAR2_ARRIVE();
        }
    } else if (w == 14) {
        // ========== MC consumer A: channels 0-31, lane = sample ============
        float accW = 0.0f;
        for (int s = 0; s <= len; s++) {
            if (s > 0) BAR2_SYNC();                     // site s staged
            const float dtl = s_dt[s];
            const float u   = s_u[s & 3][lane];
            const float4* st = s_mc[s & 1];
            float a0 = 0.0f, a1 = 0.0f;
#pragma unroll 8
            for (int ch = 0; ch < 32; ch += 2) {
                const float4 t0 = st[ch], t1 = st[ch + 1];
                a0 = fmaf(t0.w, tanh_mufu(fmaf(t0.y, ex2f(u * t0.x), t0.z)), a0);
                a1 = fmaf(t1.w, tanh_mufu(fmaf(t1.y, ex2f(u * t1.x), t1.z)), a1);
            }
            BAR3_SYNC();                                // warp15 partial ready
            const float tot = a0 + a1 + s_pp[s & 1][lane] + bfv;
            if (lane < NMC)
                accW = fmaf(fsoftplus(tot), dtl, accW);
        }
        // sum accW over 30 sample lanes (lanes 30,31 contributed 0)
        float sw = (lane < NMC) ? accW : 0.0f;
#pragma unroll
        for (int off = 16; off; off >>= 1)
            sw += __shfl_xor_sync(0xFFFFFFFFu, sw, off);
        if (lane == 0) s_red[0] = sw;
    } else {
        // ========== MC consumer B: channels 32-63 + event term =============
        float accEv = 0.0f, accDt = 0.0f;
        for (int s = 0; s <= len; s++) {
            if (s > 0) BAR2_SYNC();                     // site s staged
            const float dtl = s_dt[s];
            const float u   = s_u[s & 3][lane];
            const float4* st = s_mc[s & 1];
            float a0 = 0.0f, a1 = 0.0f;
#pragma unroll 8
            for (int ch = 32; ch < 64; ch += 2) {
                const float4 t0 = st[ch], t1 = st[ch + 1];
                a0 = fmaf(t0.w, tanh_mufu(fmaf(t0.y, ex2f(u * t0.x), t0.z)), a0);
                a1 = fmaf(t1.w, tanh_mufu(fmaf(t1.y, ex2f(u * t1.x), t1.z)), a1);
            }
            s_pp[s & 1][lane] = a0 + a1;
            BAR3_ARRIVE();                              // publish partial
            accDt += dtl;
            if (s < len) {                              // event log-term
                float q = s_bw[s & 1][lane] + s_bw[s & 1][lane + 32];
#pragma unroll
                for (int off = 16; off; off >>= 1)
                    q += __shfl_xor_sync(0xFFFFFFFFu, q, off);
                accEv += flog(fsoftplus(q + bfv) + EPS_L);
            }
        }
        if (lane == 0) { s_red[1] = accEv; s_red[2] = accDt; }
    }

    __syncthreads();
    if (j == 0) {
        g_part[b] = s_red[1] - (s_red[0] * (1.0f / NMC) + EPS_L * s_red[2]);
        __threadfence();
        if (atomicAdd(&g_done, 1u) == BATCH - 1) {      // last CTA reduces
            float S = 0.0f;
#pragma unroll 8
            for (int k = 0; k < BATCH; k++) S += g_part[k];
            out[0] = -S * (1.0f / BATCH);
            g_done = 0u;                                // reset for replays
        }
    }
}

// ------------------------------- launcher ------------------------------------
extern "C" void kernel_launch(void* const* d_in, const int* in_sizes, int n_in,
                              void* d_out, int out_size)
{
    const float* seq  = nullptr;
    const float* Wrec = nullptr;
    const float* brec = nullptr;
    const float* Wf   = nullptr;
    const float* bf   = nullptr;
    const int*   lens = nullptr;
    for (int i = 0; i < n_in; i++) {
        const int s = in_sizes[i];
        if      (s == BATCH * MAXL)     seq  = (const float*)d_in[i];
        else if (s == 65 * NCOL)        Wrec = (const float*)d_in[i];
        else if (s == NCOL)             brec = (const float*)d_in[i];
        else if (s == 1)                bf   = (const float*)d_in[i];
        else if (s == HID) {
            if (!Wf) Wf = (const float*)d_in[i];
            else     lens = (const int*)d_in[i];
        }
    }

    hawkes_kernel<<<BATCH, NTHR>>>(seq, Wrec, brec, Wf, bf, lens, (float*)d_out);
}

// round 11
// speedup vs baseline: 1.8144x; 1.1409x over previous
#include <cuda_runtime.h>
#include <cstdint>

// ---------------------------------------------------------------------------
// LSTM Neural Hawkes Process NLL  (B=64, L=1024, H=64)
// R11: back to the proven split (scan kernel + separate MC kernel + reduce).
// Scan upgraded: SPLIT-K producers — 896 threads, 2 threads per GEMM column
// (each does half the 65-dot, combined by one shfl_xor) -> half the serial
// chain, 7 warps/SMSP to hide latency. Asymmetric bar2 (epilogue arrives,
// never waits), state STGs after the arrive, branchless nonlinearities.
// ---------------------------------------------------------------------------

#define BATCH   64
#define MAXL    1024
#define LP1     1025
#define HID     64
#define NCOL    448
#define NTHR    896
#define NMC     30
#define T_END   100.0f
#define EPS_L   1e-10f
#define TOTAL   (BATCH * LP1)          // 65600
#define LOG2E   1.4426950408889634f
#define LN2     0.6931471805599453f

// ------------------------- device scratch (no mallocs) ---------------------
__device__ float4 g_state [TOTAL * HID];   // {c, cbar, o, dec}
__device__ float  g_before[TOTAL * HID];
__device__ float  g_dt    [TOTAL];
__device__ float  g_part  [TOTAL];

// ------------------------------ fast math -----------------------------------
__device__ __forceinline__ float ex2f(float x){ float y; asm("ex2.approx.f32 %0,%1;":"=f"(y):"f"(x)); return y; }
__device__ __forceinline__ float lg2f(float x){ float y; asm("lg2.approx.f32 %0,%1;":"=f"(y):"f"(x)); return y; }
__device__ __forceinline__ float tanh_mufu(float x){ float y; asm("tanh.approx.f32 %0,%1;":"=f"(y):"f"(x)); return y; }
__device__ __forceinline__ float fsoftplus(float x){
    return fmaxf(x, 0.0f) + LN2 * lg2f(1.0f + ex2f(-fabsf(x) * LOG2E));
}
__device__ __forceinline__ float flog(float x){ return LN2 * lg2f(x); }

// ------------------------------ packed f32x2 --------------------------------
__device__ __forceinline__ void fma2(unsigned long long& d, unsigned long long a, unsigned long long b){
    asm("fma.rn.f32x2 %0, %1, %2, %0;" : "+l"(d) : "l"(a), "l"(b));
}
__device__ __forceinline__ void add2(unsigned long long& d, unsigned long long a){
    asm("add.rn.f32x2 %0, %1, %0;" : "+l"(d) : "l"(a));
}
__device__ __forceinline__ unsigned long long pack2(float lo, float hi){
    unsigned long long r; asm("mov.b64 %0, {%1,%2};" : "=l"(r) : "f"(lo), "f"(hi)); return r;
}
__device__ __forceinline__ float2 unpack2(unsigned long long v){
    float2 r; asm("mov.b64 {%0,%1}, %2;" : "=f"(r.x), "=f"(r.y) : "l"(v)); return r;
}

// ------------------------------ named barriers ------------------------------
// bar1 (896): producers arrive, epilogue syncs   (gates ready)
// bar2 (896): producers sync,  epilogue arrives  (h ready)
// bar3 (128): epilogue-internal s_h visibility across its 4 warps
#define BAR1_ARRIVE() asm volatile("bar.arrive 1, 896;" ::: "memory")
#define BAR1_SYNC()   asm volatile("bar.sync   1, 896;" ::: "memory")
#define BAR2_ARRIVE() asm volatile("bar.arrive 2, 896;" ::: "memory")
#define BAR2_SYNC()   asm volatile("bar.sync   2, 896;" ::: "memory")
#define BAR3_SYNC()   asm volatile("bar.sync   3, 128;" ::: "memory")

// ------------------------------ Threefry-2x32-20 ----------------------------
__device__ __forceinline__ uint32_t rotl32(uint32_t x, int r){ return (x << r) | (x >> (32 - r)); }
__device__ __forceinline__ float tf_uniform(uint32_t flat){
    // JAX partitionable threefry, key (0,42): bits = out0 ^ out1
    uint32_t k0 = 0u, k1 = 42u, ks2 = k0 ^ k1 ^ 0x1BD11BDAu;
    uint32_t x0 = 0u + k0, x1 = flat + k1;
#define TF_R(r) { x0 += x1; x1 = rotl32(x1, (r)); x1 ^= x0; }
    TF_R(13) TF_R(15) TF_R(26) TF_R(6)   x0 += k1;  x1 += ks2 + 1u;
    TF_R(17) TF_R(29) TF_R(16) TF_R(24)  x0 += ks2; x1 += k0  + 2u;
    TF_R(13) TF_R(15) TF_R(26) TF_R(6)   x0 += k0;  x1 += k1  + 3u;
    TF_R(17) TF_R(29) TF_R(16) TF_R(24)  x0 += k1;  x1 += ks2 + 4u;
    TF_R(13) TF_R(15) TF_R(26) TF_R(6)   x0 += ks2; x1 += k0  + 5u;
#undef TF_R
    uint32_t bits = x0 ^ x1;
    return __uint_as_float((bits >> 9) | 0x3F800000u) - 1.0f;
}

// half-column dot: 16 packed f32x2 FMAs against h[half*32 .. half*32+32)
__device__ __forceinline__ float half_dot(const float* sh, const unsigned long long* w2,
                                          int half, float base)
{
    unsigned long long a0 = 0ull, a1 = 0ull, a2 = 0ull, a3 = 0ull;
    const ulonglong2* h2 = reinterpret_cast<const ulonglong2*>(sh) + half * 8;
#pragma unroll
    for (int q = 0; q < 4; q++) {
        ulonglong2 u = h2[2*q], v = h2[2*q + 1];
        fma2(a0, w2[4*q + 0], u.x);
        fma2(a1, w2[4*q + 1], u.y);
        fma2(a2, w2[4*q + 2], v.x);
        fma2(a3, w2[4*q + 3], v.y);
    }
    add2(a0, a1); add2(a2, a3); add2(a0, a2);
    float2 r = unpack2(a0);
    return (r.x + r.y) + base;
}

// ------------------------------ Kernel 1: scan -------------------------------
// One CTA per batch, 896 threads. Thread j handles column c = j>>1,
// half = j&1 (h[0:32) or h[32:64)). Pair combines via shfl_xor(1).
// Columns 0..383 (warps 0-23) = producer gates 0..5; columns 384..447
// (warps 24-27) = gate 6 + epilogue on even lanes.
__global__ void __launch_bounds__(NTHR, 1)
scan_kernel(const float* __restrict__ seq,    // [B, L, 1]
            const float* __restrict__ Wrec,   // [65, 448]
            const float* __restrict__ brec,   // [448]
            const int*   __restrict__ lens)   // [B]
{
    __shared__ __align__(16) float s_h[HID];
    __shared__ float s_v[384];                 // gates 0..5
    __shared__ float s_dt[LP1];

    const int b    = blockIdx.x;
    const int j    = threadIdx.x;
    const int c    = j >> 1;                   // column
    const int half = j & 1;                    // K-half
    const int len  = lens[b];
    const float* sp = seq + b * MAXL;

    for (int l = j; l <= MAXL; l += NTHR) {
        float v;
        if (l < len)        v = (l == 0) ? sp[0] : sp[l] - sp[l - 1];
        else if (l == len)  v = T_END - sp[len - 1];
        else                v = -1.0f;
        s_dt[l] = v;
        g_dt[b * LP1 + l] = v;
    }

    // epilogue even lanes init h and site-0 state
    if (j >= 768 && half == 0) {
        const int ch = c - 384;
        s_h[ch] = 0.0f;
        g_state [(b * LP1) * HID + ch] = make_float4(0.f, 0.f, 0.f, 0.f);
        g_before[(b * LP1) * HID + ch] = 0.0f;
    }

    // this thread's 16 weight pairs: rows half*32 + {1..32} of column c
    const float w0 = Wrec[c];                  // x weight (row 0)
    const float bj = brec[c];
    unsigned long long w2[16];
#pragma unroll
    for (int k = 0; k < 16; k++) {
        const int row = half * 32 + 2 * k + 1;
        w2[k] = pack2(Wrec[row * NCOL + c], Wrec[(row + 1) * NCOL + c]);
    }

    __syncthreads();

    if (j < 768) {
        // =============== producers: columns 0..383 (gates 0..5) ============
        const int  gate = c >> 6;
        const float al = (gate == 2) ? 1.0f : 0.5f;
        const float be = (gate == 2) ? 1.0f : 0.5f;
        const float ga = (gate == 2) ? 0.0f : 0.5f;

        for (int l = 0; l < len; l++) {
            const float dt = s_dt[l];
            const float base = half ? 0.0f : fmaf(w0, dt, bj);
            float acc = half_dot(s_h, w2, half, base);
            acc += __shfl_xor_sync(0xFFFFFFFFu, acc, 1);
            const float nv = fmaf(al, tanh_mufu(be * acc), ga);
            if (half == 0) s_v[c] = nv;
            BAR1_ARRIVE();
            BAR2_SYNC();               // h(l+1) ready
        }
    } else {
        // ====== epilogue: columns 384..447 (gate 6), warps 24-27 ===========
        const int ch = c - 384;
        float ct = 0.0f, cbar = 0.0f;  // valid on even lanes

        for (int l = 0; l < len; l++) {
            const float dt = s_dt[l];
            const float base = half ? 0.0f : fmaf(w0, dt, bj);
            float acc = half_dot(s_h, w2, half, base);
            acc += __shfl_xor_sync(0xFFFFFFFFu, acc, 1);
            const float dec = fsoftplus(acc);
            const float e   = ex2f(-dec * s_dt[l + 1] * LOG2E);

            BAR1_SYNC();               // gates ready
            float c_n = 0.f, cb_n = 0.f, oG = 0.f, bef = 0.f;
            if (half == 0) {
                const float iG = s_v[ch],        fG = s_v[ 64 + ch];
                const float zG = s_v[128 + ch];  oG = s_v[192 + ch];
                const float ib = s_v[256 + ch],  fb = s_v[320 + ch];
                c_n  = fmaf(fG, ct, iG * zG);
                cb_n = fmaf(fb, cbar, ib * zG);
                const float cd = fmaf(c_n - cb_n, e, cb_n);
                bef = oG * tanh_mufu(cd);
                ct = cd; cbar = cb_n;
                s_h[ch] = bef;
            }
            BAR2_ARRIVE();             // release producers immediately

            if (half == 0) {           // state stores off the release path
                const int base2 = (b * LP1 + l + 1) * HID + ch;
                g_state [base2] = make_float4(c_n, cb_n, oG, dec);
                g_before[base2] = bef;
            }
            BAR3_SYNC();               // s_h visible across epilogue warps
        }
    }
}

// --------------------- Kernel 2: MC integral + log-intensity -----------------
// (proven R3 version) Warp per (b,l); lane = MC sample; per-channel params
// pre-transformed into shared {m, A, cbar, o*wf}; no in-loop shuffles.
__global__ void __launch_bounds__(256, 8)
mc_kernel(const float* __restrict__ Wf,    // [64]
          const float* __restrict__ bf,    // [1]
          const int*   __restrict__ lens)  // [B]
{
    __shared__ __align__(16) float4 s_st[8][HID];

    const int warp = threadIdx.x >> 5;
    const int wid  = blockIdx.x * 8 + warp;
    if (wid >= TOTAL) return;
    const int lane = threadIdx.x & 31;
    const int b = wid / LP1;
    const int l = wid - b * LP1;
    const int len = lens[b];

    float out = 0.0f;
    if (l <= len) {
        const float dtl = g_dt[wid];
        const float bfv = bf[0];
        const int base = wid * HID;
        const float wf0 = Wf[lane], wf1 = Wf[lane + 32];

        const float4 s0 = g_state[base + lane];
        const float4 s1 = g_state[base + lane + 32];
        const float mscale = -dtl * LOG2E;
        s_st[warp][lane]      = make_float4(s0.w * mscale, s0.x - s0.y, s0.y, s0.z * wf0);
        s_st[warp][lane + 32] = make_float4(s1.w * mscale, s1.x - s1.y, s1.y, s1.z * wf1);

        float q = 0.0f;
        if (l < len)
            q = fmaf(g_before[base + lane], wf0, g_before[base + lane + 32] * wf1);
        __syncwarp();

        float sp = 0.0f;
        if (lane < NMC) {
            const float u = tf_uniform((uint32_t)lane * (uint32_t)TOTAL + (uint32_t)wid);
            float acc0 = 0.0f, acc1 = 0.0f;
            const float4* st = s_st[warp];
#pragma unroll 8
            for (int ch = 0; ch < HID; ch += 2) {
                const float4 t0 = st[ch], t1 = st[ch + 1];
                acc0 = fmaf(t0.w, tanh_mufu(fmaf(t0.y, ex2f(u * t0.x), t0.z)), acc0);
                acc1 = fmaf(t1.w, tanh_mufu(fmaf(t1.y, ex2f(u * t1.x), t1.z)), acc1);
            }
            sp = fsoftplus(acc0 + acc1 + bfv);
        }
#pragma unroll
        for (int off = 16; off; off >>= 1) {
            sp += __shfl_xor_sync(0xFFFFFFFFu, sp, off);
            q  += __shfl_xor_sync(0xFFFFFFFFu, q,  off);
        }
        const float lamb_int = (sp * (1.0f / NMC) + EPS_L) * dtl;
        float ev = 0.0f;
        if (l < len) ev = flog(fsoftplus(q + bfv) + EPS_L);
        out = ev - lamb_int;
    }
    if (lane == 0) g_part[wid] = out;
}

// --------------------------- Kernel 3: reduction -----------------------------
__global__ void __launch_bounds__(1024, 1)
reduce_kernel(float* __restrict__ out)
{
    __shared__ float sh[1024];
    const int t = threadIdx.x;
    float s = 0.0f;
    for (int i = t; i < TOTAL; i += 1024) s += g_part[i];
    sh[t] = s;
    __syncthreads();
#pragma unroll
    for (int ofs = 512; ofs; ofs >>= 1) {
        if (t < ofs) sh[t] += sh[t + ofs];
        __syncthreads();
    }
    if (t == 0) out[0] = -sh[0] * (1.0f / BATCH);
}

// ------------------------------- launcher ------------------------------------
extern "C" void kernel_launch(void* const* d_in, const int* in_sizes, int n_in,
                              void* d_out, int out_size)
{
    const float* seq  = nullptr;
    const float* Wrec = nullptr;
    const float* brec = nullptr;
    const float* Wf   = nullptr;
    const float* bf   = nullptr;
    const int*   lens = nullptr;
    for (int i = 0; i < n_in; i++) {
        const int s = in_sizes[i];
        if      (s == BATCH * MAXL)     seq  = (const float*)d_in[i];
        else if (s == 65 * NCOL)        Wrec = (const float*)d_in[i];
        else if (s == NCOL)             brec = (const float*)d_in[i];
        else if (s == 1)                bf   = (const float*)d_in[i];
        else if (s == HID) {
            if (!Wf) Wf = (const float*)d_in[i];
            else     lens = (const int*)d_in[i];
        }
    }

    scan_kernel<<<BATCH, NTHR>>>(seq, Wrec, brec, lens);
    mc_kernel<<<(TOTAL + 7) / 8, 256>>>(Wf, bf, lens);
    reduce_kernel<<<1, 1024>>>((float*)d_out);
}

// round 12
// speedup vs baseline: 2.7040x; 1.4903x over previous
#include <cuda_runtime.h>
#include <cstdint>

// ---------------------------------------------------------------------------
// LSTM Neural Hawkes Process NLL  (B=64, L=1024, H=64)
// R12: R3 skeleton (proven fastest) with strictly-local shavings:
//  - g_before eliminated algebraically (event term = MC hidden at u=1,
//    computed by spare lane 30 in mc_kernel)  -> -16.8MB traffic, -1 STG/step
//  - scan epilogue: bar2 ARRIVE (not sync), g_state STG after the arrive
//    (off the producers' release path), bar3(64) for epi-internal h visibility
//  - branchless producer nonlinearities (no BSSY/BSYNC)
//  - final reduction fused into mc_kernel (deterministic last-block tree)
// ---------------------------------------------------------------------------

#define BATCH   64
#define MAXL    1024
#define LP1     1025
#define HID     64
#define NCOL    448
#define NMC     30
#define T_END   100.0f
#define EPS_L   1e-10f
#define TOTAL   (BATCH * LP1)          // 65600
#define LOG2E   1.4426950408889634f
#define LN2     0.6931471805599453f
#define MC_BLOCKS ((TOTAL + 7) / 8)    // 8200

// ------------------------- device scratch (no mallocs) ---------------------
__device__ float4   g_state[TOTAL * HID];  // {c, cbar, o, dec}
__device__ float    g_dt   [TOTAL];
__device__ float    g_part [TOTAL];
__device__ unsigned g_done = 0;

// ------------------------------ fast math -----------------------------------
__device__ __forceinline__ float ex2f(float x){ float y; asm("ex2.approx.f32 %0,%1;":"=f"(y):"f"(x)); return y; }
__device__ __forceinline__ float lg2f(float x){ float y; asm("lg2.approx.f32 %0,%1;":"=f"(y):"f"(x)); return y; }
__device__ __forceinline__ float tanh_mufu(float x){ float y; asm("tanh.approx.f32 %0,%1;":"=f"(y):"f"(x)); return y; }
__device__ __forceinline__ float fsoftplus(float x){
    return fmaxf(x, 0.0f) + LN2 * lg2f(1.0f + ex2f(-fabsf(x) * LOG2E));
}
__device__ __forceinline__ float flog(float x){ return LN2 * lg2f(x); }

// ------------------------------ packed f32x2 --------------------------------
__device__ __forceinline__ void fma2(unsigned long long& d, unsigned long long a, unsigned long long b){
    asm("fma.rn.f32x2 %0, %1, %2, %0;" : "+l"(d) : "l"(a), "l"(b));
}
__device__ __forceinline__ void add2(unsigned long long& d, unsigned long long a){
    asm("add.rn.f32x2 %0, %1, %0;" : "+l"(d) : "l"(a));
}
__device__ __forceinline__ unsigned long long pack2(float lo, float hi){
    unsigned long long r; asm("mov.b64 %0, {%1,%2};" : "=l"(r) : "f"(lo), "f"(hi)); return r;
}
__device__ __forceinline__ float2 unpack2(unsigned long long v){
    float2 r; asm("mov.b64 {%0,%1}, %2;" : "=f"(r.x), "=f"(r.y) : "l"(v)); return r;
}

// ------------------------------ named barriers ------------------------------
// bar1 (448): producers arrive, epilogue syncs   (gates ready)
// bar2 (448): producers sync,  epilogue arrives  (h ready)
// bar3 (64) : epilogue-internal s_h visibility across its 2 warps
#define BAR1_ARRIVE() asm volatile("bar.arrive 1, 448;" ::: "memory")
#define BAR1_SYNC()   asm volatile("bar.sync   1, 448;" ::: "memory")
#define BAR2_ARRIVE() asm volatile("bar.arrive 2, 448;" ::: "memory")
#define BAR2_SYNC()   asm volatile("bar.sync   2, 448;" ::: "memory")
#define BAR3_SYNC()   asm volatile("bar.sync   3, 64;"  ::: "memory")

// ------------------------------ Threefry-2x32-20 ----------------------------
__device__ __forceinline__ uint32_t rotl32(uint32_t x, int r){ return (x << r) | (x >> (32 - r)); }
__device__ __forceinline__ float tf_uniform(uint32_t flat){
    // JAX partitionable threefry, key (0,42): bits = out0 ^ out1
    uint32_t k0 = 0u, k1 = 42u, ks2 = k0 ^ k1 ^ 0x1BD11BDAu;
    uint32_t x0 = 0u + k0, x1 = flat + k1;
#define TF_R(r) { x0 += x1; x1 = rotl32(x1, (r)); x1 ^= x0; }
    TF_R(13) TF_R(15) TF_R(26) TF_R(6)   x0 += k1;  x1 += ks2 + 1u;
    TF_R(17) TF_R(29) TF_R(16) TF_R(24)  x0 += ks2; x1 += k0  + 2u;
    TF_R(13) TF_R(15) TF_R(26) TF_R(6)   x0 += k0;  x1 += k1  + 3u;
    TF_R(17) TF_R(29) TF_R(16) TF_R(24)  x0 += k1;  x1 += ks2 + 4u;
    TF_R(13) TF_R(15) TF_R(26) TF_R(6)   x0 += ks2; x1 += k0  + 5u;
#undef TF_R
    uint32_t bits = x0 ^ x1;
    return __uint_as_float((bits >> 9) | 0x3F800000u) - 1.0f;
}

// 65-long packed-f32x2 column dot against shared h
__device__ __forceinline__ float col_dot(const float* sh, const unsigned long long* w2,
                                         float w0, float bj, float dt)
{
    unsigned long long a0 = 0ull, a1 = 0ull, a2 = 0ull, a3 = 0ull;
    const ulonglong2* h2 = reinterpret_cast<const ulonglong2*>(sh);
#pragma unroll
    for (int q = 0; q < 4; q++) {
        ulonglong2 u = h2[2*q], v = h2[2*q + 1];
        fma2(a0, w2[4*q + 0],  u.x);
        fma2(a1, w2[4*q + 1],  u.y);
        fma2(a2, w2[4*q + 2],  v.x);
        fma2(a3, w2[4*q + 3],  v.y);
        ulonglong2 s = h2[2*q + 8], t = h2[2*q + 9];
        fma2(a0, w2[4*q + 16], s.x);
        fma2(a1, w2[4*q + 17], s.y);
        fma2(a2, w2[4*q + 18], t.x);
        fma2(a3, w2[4*q + 19], t.y);
    }
    add2(a0, a1); add2(a2, a3); add2(a0, a2);
    float2 r = unpack2(a0);
    return (r.x + r.y) + fmaf(w0, dt, bj);
}

// ------------------------------ Kernel 1: scan -------------------------------
// One CTA per batch, 448 threads (thread j = GEMM column j).
// Warps 0-11 = producers (gates 0..5); warps 12-13 = gate-6 + epilogue.
__global__ void __launch_bounds__(NCOL, 1)
scan_kernel(const float* __restrict__ seq,    // [B, L, 1]
            const float* __restrict__ Wrec,   // [65, 448]
            const float* __restrict__ brec,   // [448]
            const int*   __restrict__ lens)   // [B]
{
    __shared__ __align__(16) float s_h[HID];
    __shared__ float s_v[384];
    __shared__ float s_dt[LP1];

    const int b   = blockIdx.x;
    const int j   = threadIdx.x;
    const int len = lens[b];
    const float* sp = seq + b * MAXL;

    for (int l = j; l <= MAXL; l += NCOL) {
        float v;
        if (l < len)        v = (l == 0) ? sp[0] : sp[l] - sp[l - 1];
        else if (l == len)  v = T_END - sp[len - 1];
        else                v = -1.0f;
        s_dt[l] = v;
        g_dt[b * LP1 + l] = v;
    }

    if (j >= 384) {                     // epilogue threads init h + site 0
        const int ch = j - 384;
        s_h[ch] = 0.0f;
        g_state[(b * LP1) * HID + ch] = make_float4(0.f, 0.f, 0.f, 0.f);
    }

    // column weights: row 0 (x) scalar + 32 packed f32x2 pairs
    const float w0 = Wrec[j];
    const float bj = brec[j];
    unsigned long long w2[32];
#pragma unroll
    for (int k = 0; k < 32; k++)
        w2[k] = pack2(Wrec[(2*k + 1) * NCOL + j], Wrec[(2*k + 2) * NCOL + j]);

    __syncthreads();

    if (j < 384) {
        // =============== producers: warps 0-11 (gates 0..5) ================
        const int  gate = j >> 6;       // branchless: tanh(x) or 0.5*tanh(0.5x)+0.5
        const float al = (gate == 2) ? 1.0f : 0.5f;
        const float be = (gate == 2) ? 1.0f : 0.5f;
        const float ga = (gate == 2) ? 0.0f : 0.5f;
        for (int l = 0; l < len; l++) {
            const float acc = col_dot(s_h, w2, w0, bj, s_dt[l]);
            s_v[j] = fmaf(al, tanh_mufu(be * acc), ga);
            BAR1_ARRIVE();
            BAR2_SYNC();                // h(l+1) ready
        }
    } else {
        // ============ epilogue: warps 12,13 (= gate-6 columns) =============
        const int ch = j - 384;
        float ct = 0.0f, cbar = 0.0f;
        for (int l = 0; l < len; l++) {
            const float acc = col_dot(s_h, w2, w0, bj, s_dt[l]);
            const float dec = fsoftplus(acc);
            const float e   = ex2f(-dec * s_dt[l + 1] * LOG2E);

            BAR1_SYNC();                // gates ready
            const float iG = s_v[ch],        fG = s_v[ 64 + ch];
            const float zG = s_v[128 + ch],  oG = s_v[192 + ch];
            const float ib = s_v[256 + ch],  fb = s_v[320 + ch];
            const float c  = fmaf(fG, ct, iG * zG);
            const float cb = fmaf(fb, cbar, ib * zG);
            const float cd = fmaf(c - cb, e, cb);
            const float bef = oG * tanh_mufu(cd);
            ct = cd; cbar = cb;
            s_h[ch] = bef;
            BAR2_ARRIVE();              // release producers immediately

            // state store OFF the producers' release path
            g_state[(b * LP1 + l + 1) * HID + ch] = make_float4(c, cb, oG, dec);
            BAR3_SYNC();                // s_h visible across the 2 epi warps
        }
    }
}

// ---------------- Kernel 2: MC integral + event term + reduction -------------
// Warp per (b,l); lane = MC sample (lanes 0-29), lane 30 = u=1 which
// reproduces `before` algebraically (event log-term) — no g_before array.
// Deterministic last-block reduction finishes the NLL.
__global__ void __launch_bounds__(256, 8)
mc_kernel(const float* __restrict__ Wf,    // [64]
          const float* __restrict__ bf,    // [1]
          const int*   __restrict__ lens,  // [B]
          float*       __restrict__ out)
{
    __shared__ __align__(16) float4 s_st[8][HID];
    __shared__ bool s_last;

    const int warp = threadIdx.x >> 5;
    const int wid  = blockIdx.x * 8 + warp;
    const int lane = threadIdx.x & 31;

    if (wid < TOTAL) {
        const int b = wid / LP1;
        const int l = wid - b * LP1;
        const int len = lens[b];

        float res = 0.0f;
        if (l <= len) {
            const float dtl = g_dt[wid];
            const float bfv = bf[0];
            const int base = wid * HID;
            const float wf0 = Wf[lane], wf1 = Wf[lane + 32];

            const float4 s0 = g_state[base + lane];
            const float4 s1 = g_state[base + lane + 32];
            const float mscale = -dtl * LOG2E;
            s_st[warp][lane]      = make_float4(s0.w * mscale, s0.x - s0.y, s0.y, s0.z * wf0);
            s_st[warp][lane + 32] = make_float4(s1.w * mscale, s1.x - s1.y, s1.y, s1.z * wf1);
            __syncwarp();

            // lane < 30: sample u_lane; lanes 30,31: u = 1 (lane 30's dot
            // equals before·Wf — the event term's linear part)
            float u = 1.0f;
            if (lane < NMC)
                u = tf_uniform((uint32_t)lane * (uint32_t)TOTAL + (uint32_t)wid);

            float a0 = 0.0f, a1 = 0.0f;
            const float4* st = s_st[warp];
#pragma unroll 8
            for (int ch = 0; ch < HID; ch += 2) {
                const float4 t0 = st[ch], t1 = st[ch + 1];
                a0 = fmaf(t0.w, tanh_mufu(fmaf(t0.y, ex2f(u * t0.x), t0.z)), a0);
                a1 = fmaf(t1.w, tanh_mufu(fmaf(t1.y, ex2f(u * t1.x), t1.z)), a1);
            }
            const float dot = a0 + a1;

            float sp = (lane < NMC) ? fsoftplus(dot + bfv) : 0.0f;
#pragma unroll
            for (int off = 16; off; off >>= 1)
                sp += __shfl_xor_sync(0xFFFFFFFFu, sp, off);
            const float q = __shfl_sync(0xFFFFFFFFu, dot, 30);

            const float lamb_int = (sp * (1.0f / NMC) + EPS_L) * dtl;
            float ev = 0.0f;
            if (l < len) ev = flog(fsoftplus(q + bfv) + EPS_L);
            res = ev - lamb_int;
        }
        if (lane == 0) g_part[wid] = res;
    }

    // ---- deterministic last-block reduction ----
    __threadfence();
    __syncthreads();
    if (threadIdx.x == 0)
        s_last = (atomicAdd(&g_done, 1u) == (unsigned)(gridDim.x - 1));
    __syncthreads();
    if (s_last) {
        __shared__ float sh[256];
        float s = 0.0f;
        for (int i = threadIdx.x; i < TOTAL; i += 256) s += g_part[i];
        sh[threadIdx.x] = s;
        __syncthreads();
#pragma unroll
        for (int ofs = 128; ofs; ofs >>= 1) {
            if (threadIdx.x < ofs) sh[threadIdx.x] += sh[threadIdx.x + ofs];
            __syncthreads();
        }
        if (threadIdx.x == 0) {
            out[0] = -sh[0] * (1.0f / BATCH);
            g_done = 0u;                 // reset for graph replays
        }
    }
}

// ------------------------------- launcher ------------------------------------
extern "C" void kernel_launch(void* const* d_in, const int* in_sizes, int n_in,
                              void* d_out, int out_size)
{
    const float* seq  = nullptr;
    const float* Wrec = nullptr;
    const float* brec = nullptr;
    const float* Wf   = nullptr;
    const float* bf   = nullptr;
    const int*   lens = nullptr;
    for (int i = 0; i < n_in; i++) {
        const int s = in_sizes[i];
        if      (s == BATCH * MAXL)     seq  = (const float*)d_in[i];
        else if (s == 65 * NCOL)        Wrec = (const float*)d_in[i];
        else if (s == NCOL)             brec = (const float*)d_in[i];
        else if (s == 1)                bf   = (const float*)d_in[i];
        else if (s == HID) {
            if (!Wf) Wf = (const float*)d_in[i];
            else     lens = (const int*)d_in[i];
        }
    }

    scan_kernel<<<BATCH, NCOL>>>(seq, Wrec, brec, lens);
    mc_kernel<<<MC_BLOCKS, 256>>>(Wf, bf, lens, (float*)d_out);
}

// round 13
// speedup vs baseline: 2.8544x; 1.0556x over previous
#include <cuda_runtime.h>
#include <cstdint>

// ---------------------------------------------------------------------------
// LSTM Neural Hawkes Process NLL  (B=64, L=1024, H=64)
// R13: chunked producer/consumer overlap, ONE launch, grid 128.
//  CTA b (0..63)    : R12 scan (byte-identical fabric) + one release-store
//                     of g_flag[b] per 64 steps (after the existing bar3).
//  CTA 64+b         : MC consumer for batch b; polls g_flag[b] per chunk
//                     (1 thread), processes the chunk's 64 sites across 14
//                     warps with the proven lane=sample MC math.
//  Last consumer CTA reduces, writes out, resets flags for graph replays.
// ---------------------------------------------------------------------------

#define BATCH   64
#define MAXL    1024
#define LP1     1025
#define HID     64
#define NCOL    448
#define NMC     30
#define T_END   100.0f
#define EPS_L   1e-10f
#define TOTAL   (BATCH * LP1)          // 65600
#define LOG2E   1.4426950408889634f
#define LN2     0.6931471805599453f

// ------------------------- device scratch (no mallocs) ---------------------
__device__ float4   g_state[TOTAL * HID];  // {c, cbar, o, dec}
__device__ unsigned g_flag [BATCH];        // chunks published (reset at end)
__device__ float    g_part [BATCH];
__device__ unsigned g_done = 0;

// ------------------------------ fast math -----------------------------------
__device__ __forceinline__ float ex2f(float x){ float y; asm("ex2.approx.f32 %0,%1;":"=f"(y):"f"(x)); return y; }
__device__ __forceinline__ float lg2f(float x){ float y; asm("lg2.approx.f32 %0,%1;":"=f"(y):"f"(x)); return y; }
__device__ __forceinline__ float tanh_mufu(float x){ float y; asm("tanh.approx.f32 %0,%1;":"=f"(y):"f"(x)); return y; }
__device__ __forceinline__ float fsoftplus(float x){
    return fmaxf(x, 0.0f) + LN2 * lg2f(1.0f + ex2f(-fabsf(x) * LOG2E));
}
__device__ __forceinline__ float flog(float x){ return LN2 * lg2f(x); }

// ------------------------------ packed f32x2 --------------------------------
__device__ __forceinline__ void fma2(unsigned long long& d, unsigned long long a, unsigned long long b){
    asm("fma.rn.f32x2 %0, %1, %2, %0;" : "+l"(d) : "l"(a), "l"(b));
}
__device__ __forceinline__ void add2(unsigned long long& d, unsigned long long a){
    asm("add.rn.f32x2 %0, %1, %0;" : "+l"(d) : "l"(a));
}
__device__ __forceinline__ unsigned long long pack2(float lo, float hi){
    unsigned long long r; asm("mov.b64 %0, {%1,%2};" : "=l"(r) : "f"(lo), "f"(hi)); return r;
}
__device__ __forceinline__ float2 unpack2(unsigned long long v){
    float2 r; asm("mov.b64 {%0,%1}, %2;" : "=f"(r.x), "=f"(r.y) : "l"(v)); return r;
}

// --------------------------- publish primitives ------------------------------
__device__ __forceinline__ void st_release_u32(unsigned* p, unsigned v){
    asm volatile("st.release.gpu.global.u32 [%0], %1;" :: "l"(p), "r"(v) : "memory");
}
__device__ __forceinline__ unsigned ld_acquire_u32(const unsigned* p){
    unsigned v;
    asm volatile("ld.acquire.gpu.global.u32 %0, [%1];" : "=r"(v) : "l"(p) : "memory");
    return v;
}

// ------------------------------ named barriers ------------------------------
#define BAR1_ARRIVE() asm volatile("bar.arrive 1, 448;" ::: "memory")
#define BAR1_SYNC()   asm volatile("bar.sync   1, 448;" ::: "memory")
#define BAR2_ARRIVE() asm volatile("bar.arrive 2, 448;" ::: "memory")
#define BAR2_SYNC()   asm volatile("bar.sync   2, 448;" ::: "memory")
#define BAR3_SYNC()   asm volatile("bar.sync   3, 64;"  ::: "memory")

// ------------------------------ Threefry-2x32-20 ----------------------------
__device__ __forceinline__ uint32_t rotl32(uint32_t x, int r){ return (x << r) | (x >> (32 - r)); }
__device__ __forceinline__ float tf_uniform(uint32_t flat){
    // JAX partitionable threefry, key (0,42): bits = out0 ^ out1
    uint32_t k0 = 0u, k1 = 42u, ks2 = k0 ^ k1 ^ 0x1BD11BDAu;
    uint32_t x0 = 0u + k0, x1 = flat + k1;
#define TF_R(r) { x0 += x1; x1 = rotl32(x1, (r)); x1 ^= x0; }
    TF_R(13) TF_R(15) TF_R(26) TF_R(6)   x0 += k1;  x1 += ks2 + 1u;
    TF_R(17) TF_R(29) TF_R(16) TF_R(24)  x0 += ks2; x1 += k0  + 2u;
    TF_R(13) TF_R(15) TF_R(26) TF_R(6)   x0 += k0;  x1 += k1  + 3u;
    TF_R(17) TF_R(29) TF_R(16) TF_R(24)  x0 += k1;  x1 += ks2 + 4u;
    TF_R(13) TF_R(15) TF_R(26) TF_R(6)   x0 += ks2; x1 += k0  + 5u;
#undef TF_R
    uint32_t bits = x0 ^ x1;
    return __uint_as_float((bits >> 9) | 0x3F800000u) - 1.0f;
}

// 65-long packed-f32x2 column dot against shared h
__device__ __forceinline__ float col_dot(const float* sh, const unsigned long long* w2,
                                         float w0, float bj, float dt)
{
    unsigned long long a0 = 0ull, a1 = 0ull, a2 = 0ull, a3 = 0ull;
    const ulonglong2* h2 = reinterpret_cast<const ulonglong2*>(sh);
#pragma unroll
    for (int q = 0; q < 4; q++) {
        ulonglong2 u = h2[2*q], v = h2[2*q + 1];
        fma2(a0, w2[4*q + 0],  u.x);
        fma2(a1, w2[4*q + 1],  u.y);
        fma2(a2, w2[4*q + 2],  v.x);
        fma2(a3, w2[4*q + 3],  v.y);
        ulonglong2 s = h2[2*q + 8], t = h2[2*q + 9];
        fma2(a0, w2[4*q + 16], s.x);
        fma2(a1, w2[4*q + 17], s.y);
        fma2(a2, w2[4*q + 18], t.x);
        fma2(a3, w2[4*q + 19], t.y);
    }
    add2(a0, a1); add2(a2, a3); add2(a0, a2);
    float2 r = unpack2(a0);
    return (r.x + r.y) + fmaf(w0, dt, bj);
}

// --------------------------- shared memory union -----------------------------
union SmemU {
    struct {
        float h[HID];
        float v[384];
        float dt[LP1];
    } scan;
    struct {
        float4 stg[14][HID];   // per-warp MC staging
        float  red[14];
        unsigned flag;
    } mc;
};

// ------------------------------- main kernel ---------------------------------
__global__ void __launch_bounds__(NCOL, 1)
hawkes_kernel(const float* __restrict__ seq,    // [B, L, 1]
              const float* __restrict__ Wrec,   // [65, 448]
              const float* __restrict__ brec,   // [448]
              const float* __restrict__ Wf,     // [64]
              const float* __restrict__ bf,     // [1]
              const int*   __restrict__ lens,   // [B]
              float*       __restrict__ out)
{
    __shared__ SmemU smem;

    const int j    = threadIdx.x;
    const int w    = j >> 5;
    const int lane = j & 31;

    if (blockIdx.x < BATCH) {
        // ===================== SCAN role (R12, proven) =====================
        const int b   = blockIdx.x;
        const int len = lens[b];
        const float* sp = seq + b * MAXL;
        float* s_h  = smem.scan.h;
        float* s_v  = smem.scan.v;
        float* s_dt = smem.scan.dt;

        for (int l = j; l <= MAXL; l += NCOL) {
            float v;
            if (l < len)        v = (l == 0) ? sp[0] : sp[l] - sp[l - 1];
            else if (l == len)  v = T_END - sp[len - 1];
            else                v = -1.0f;
            s_dt[l] = v;
        }

        if (j >= 384) {                 // epilogue threads init h + site 0
            const int ch = j - 384;
            s_h[ch] = 0.0f;
            g_state[(b * LP1) * HID + ch] = make_float4(0.f, 0.f, 0.f, 0.f);
        }

        const float w0 = Wrec[j];
        const float bj = brec[j];
        unsigned long long w2[32];
#pragma unroll
        for (int k = 0; k < 32; k++)
            w2[k] = pack2(Wrec[(2*k + 1) * NCOL + j], Wrec[(2*k + 2) * NCOL + j]);

        __syncthreads();

        if (j < 384) {
            // ----- producers: warps 0-11 (gates 0..5), branchless -----
            const int  gate = j >> 6;
            const float al = (gate == 2) ? 1.0f : 0.5f;
            const float be = (gate == 2) ? 1.0f : 0.5f;
            const float ga = (gate == 2) ? 0.0f : 0.5f;
            for (int l = 0; l < len; l++) {
                const float acc = col_dot(s_h, w2, w0, bj, s_dt[l]);
                s_v[j] = fmaf(al, tanh_mufu(be * acc), ga);
                BAR1_ARRIVE();
                BAR2_SYNC();            // h(l+1) ready
            }
        } else {
            // ----- epilogue: warps 12,13 (= gate-6 columns) -----
            const int ch = j - 384;
            float ct = 0.0f, cbar = 0.0f;
            for (int l = 0; l < len; l++) {
                const float acc = col_dot(s_h, w2, w0, bj, s_dt[l]);
                const float dec = fsoftplus(acc);
                const float e   = ex2f(-dec * s_dt[l + 1] * LOG2E);

                BAR1_SYNC();            // gates ready
                const float iG = s_v[ch],        fG = s_v[ 64 + ch];
                const float zG = s_v[128 + ch],  oG = s_v[192 + ch];
                const float ib = s_v[256 + ch],  fb = s_v[320 + ch];
                const float c  = fmaf(fG, ct, iG * zG);
                const float cb = fmaf(fb, cbar, ib * zG);
                const float cd = fmaf(c - cb, e, cb);
                const float bef = oG * tanh_mufu(cd);
                ct = cd; cbar = cb;
                s_h[ch] = bef;
                BAR2_ARRIVE();          // release producers immediately

                g_state[(b * LP1 + l + 1) * HID + ch] = make_float4(c, cb, oG, dec);
                BAR3_SYNC();            // orders ALL epi STGs (sites <= l+1)
                // chunk publish: 1 predicated store per 64 steps, ch0 only
                if (ch == 0 && ((l + 1) & 63) == 0)
                    st_release_u32(&g_flag[b], (unsigned)((l + 1) >> 6));
            }
            if (ch == 0)
                st_release_u32(&g_flag[b], 1u << 20);   // everything published
        }
    } else {
        // ===================== MC CONSUMER role ============================
        const int b   = blockIdx.x - BATCH;
        const int len = lens[b];
        const float bfv = bf[0];
        const float* sp = seq + b * MAXL;
        const float wf0 = Wf[lane], wf1 = Wf[lane + 32];
        float4* stg = smem.mc.stg[w];

        float acc = 0.0f;               // lane 0 per warp: sum(ev - lamb_int)

        for (int k = 0; 64 * k <= len; k++) {
            if (j == 0) {               // poll for chunk k's sites (<= 64k+63)
                while (ld_acquire_u32(&g_flag[b]) < (unsigned)(k + 1))
                    __nanosleep(256);
            }
            __syncthreads();            // visibility for all threads

            const int sLim = min(64 * k + 63, len);
            for (int s = 64 * k + w; s <= sLim; s += 14) {
                // dt from inputs (redundant across lanes, L1-broadcast)
                float dtl;
                if (s < len) dtl = (s == 0) ? sp[0] : sp[s] - sp[s - 1];
                else         dtl = T_END - sp[len - 1];

                const int base = (b * LP1 + s) * HID;
                const float4 s0 = g_state[base + lane];
                const float4 s1 = g_state[base + lane + 32];
                const float mscale = -dtl * LOG2E;
                stg[lane]      = make_float4(s0.w * mscale, s0.x - s0.y, s0.y, s0.z * wf0);
                stg[lane + 32] = make_float4(s1.w * mscale, s1.x - s1.y, s1.y, s1.z * wf1);
                __syncwarp();

                // lane<30: sample u; lanes 30,31: u=1 (lane30 dot = before.Wf)
                float u = 1.0f;
                if (lane < NMC)
                    u = tf_uniform((uint32_t)lane * (uint32_t)TOTAL
                                   + (uint32_t)(b * LP1 + s));
                float a0 = 0.0f, a1 = 0.0f;
#pragma unroll 8
                for (int ch = 0; ch < HID; ch += 2) {
                    const float4 t0 = stg[ch], t1 = stg[ch + 1];
                    a0 = fmaf(t0.w, tanh_mufu(fmaf(t0.y, ex2f(u * t0.x), t0.z)), a0);
                    a1 = fmaf(t1.w, tanh_mufu(fmaf(t1.y, ex2f(u * t1.x), t1.z)), a1);
                }
                const float dot = a0 + a1;

                float spv = (lane < NMC) ? fsoftplus(dot + bfv) : 0.0f;
#pragma unroll
                for (int off = 16; off; off >>= 1)
                    spv += __shfl_xor_sync(0xFFFFFFFFu, spv, off);
                const float q = __shfl_sync(0xFFFFFFFFu, dot, 30);

                if (lane == 0) {
                    const float lamb_int = (spv * (1.0f / NMC) + EPS_L) * dtl;
                    float ev = 0.0f;
                    if (s < len) ev = flog(fsoftplus(q + bfv) + EPS_L);
                    acc += ev - lamb_int;
                }
                __syncwarp();           // protect stg for next site
            }
        }

        if (lane == 0) smem.mc.red[w] = acc;
        __syncthreads();
        if (j == 0) {
            float S = 0.0f;
#pragma unroll
            for (int k = 0; k < 14; k++) S += smem.mc.red[k];
            g_part[b] = S;
            __threadfence();
            if (atomicAdd(&g_done, 1u) == (unsigned)(BATCH - 1)) {
                float T = 0.0f;
#pragma unroll 8
                for (int k = 0; k < BATCH; k++) T += g_part[k];
                out[0] = -T * (1.0f / BATCH);
                // reset for graph replays (stream order protects next run)
                for (int k = 0; k < BATCH; k++) g_flag[k] = 0u;
                g_done = 0u;
            }
        }
    }
}

// ------------------------------- launcher ------------------------------------
extern "C" void kernel_launch(void* const* d_in, const int* in_sizes, int n_in,
                              void* d_out, int out_size)
{
    const float* seq  = nullptr;
    const float* Wrec = nullptr;
    const float* brec = nullptr;
    const float* Wf   = nullptr;
    const float* bf   = nullptr;
    const int*   lens = nullptr;
    for (int i = 0; i < n_in; i++) {
        const int s = in_sizes[i];
        if      (s == BATCH * MAXL)     seq  = (const float*)d_in[i];
        else if (s == 65 * NCOL)        Wrec = (const float*)d_in[i];
        else if (s == NCOL)             brec = (const float*)d_in[i];
        else if (s == 1)                bf   = (const float*)d_in[i];
        else if (s == HID) {
            if (!Wf) Wf = (const float*)d_in[i];
            else     lens = (const int*)d_in[i];
        }
    }

    hawkes_kernel<<<2 * BATCH, NCOL>>>(seq, Wrec, brec, Wf, bf, lens, (float*)d_out);
}

// round 15
// speedup vs baseline: 3.6933x; 1.2939x over previous
#include <cuda_runtime.h>
#include <cstdint>

// ---------------------------------------------------------------------------
// LSTM Neural Hawkes Process NLL  (B=64, L=1024, H=64)
// R15: R14 (2x thread-coarsened scan + R13 overlap fabric) with the sigmoid
// constant bug fixed (ga must be 0.5 for sigmoid gates, 0 for tanh).
//  Block = 224 threads everywhere.
//  Scan CTA: thread t owns columns t and t+224 (two independent f32x2 dots).
//    warps 0-4  (t<160)  : pure producers
//    warps 5-6  (t>=160) : c1 = gate-6 column of channel ch=t-160; epilogue
//                          (bar1 sync, bar2 arrive, post-release STG,
//                           bar3(64), chunk flag publish).
//  Consumer CTA: 7 warps, lane=sample MC math, chunk-polling.
// ---------------------------------------------------------------------------

#define BATCH   64
#define MAXL    1024
#define LP1     1025
#define HID     64
#define NCOL    448
#define NTHR    224
#define NMC     30
#define T_END   100.0f
#define EPS_L   1e-10f
#define TOTAL   (BATCH * LP1)          // 65600
#define LOG2E   1.4426950408889634f
#define LN2     0.6931471805599453f

// ------------------------- device scratch (no mallocs) ---------------------
__device__ float4   g_state[TOTAL * HID];  // {c, cbar, o, dec}
__device__ unsigned g_flag [BATCH];
__device__ float    g_part [BATCH];
__device__ unsigned g_done = 0;

// ------------------------------ fast math -----------------------------------
__device__ __forceinline__ float ex2f(float x){ float y; asm("ex2.approx.f32 %0,%1;":"=f"(y):"f"(x)); return y; }
__device__ __forceinline__ float lg2f(float x){ float y; asm("lg2.approx.f32 %0,%1;":"=f"(y):"f"(x)); return y; }
__device__ __forceinline__ float tanh_mufu(float x){ float y; asm("tanh.approx.f32 %0,%1;":"=f"(y):"f"(x)); return y; }
__device__ __forceinline__ float fsoftplus(float x){
    return fmaxf(x, 0.0f) + LN2 * lg2f(1.0f + ex2f(-fabsf(x) * LOG2E));
}
__device__ __forceinline__ float flog(float x){ return LN2 * lg2f(x); }

// ------------------------------ packed f32x2 --------------------------------
__device__ __forceinline__ void fma2(unsigned long long& d, unsigned long long a, unsigned long long b){
    asm("fma.rn.f32x2 %0, %1, %2, %0;" : "+l"(d) : "l"(a), "l"(b));
}
__device__ __forceinline__ void add2(unsigned long long& d, unsigned long long a){
    asm("add.rn.f32x2 %0, %1, %0;" : "+l"(d) : "l"(a));
}
__device__ __forceinline__ unsigned long long pack2(float lo, float hi){
    unsigned long long r; asm("mov.b64 %0, {%1,%2};" : "=l"(r) : "f"(lo), "f"(hi)); return r;
}
__device__ __forceinline__ float2 unpack2(unsigned long long v){
    float2 r; asm("mov.b64 {%0,%1}, %2;" : "=f"(r.x), "=f"(r.y) : "l"(v)); return r;
}

// --------------------------- publish primitives ------------------------------
__device__ __forceinline__ void st_release_u32(unsigned* p, unsigned v){
    asm volatile("st.release.gpu.global.u32 [%0], %1;" :: "l"(p), "r"(v) : "memory");
}
__device__ __forceinline__ unsigned ld_acquire_u32(const unsigned* p){
    unsigned v;
    asm volatile("ld.acquire.gpu.global.u32 %0, [%1];" : "=r"(v) : "l"(p) : "memory");
    return v;
}

// ------------------------------ named barriers ------------------------------
#define BAR1_ARRIVE() asm volatile("bar.arrive 1, 224;" ::: "memory")
#define BAR1_SYNC()   asm volatile("bar.sync   1, 224;" ::: "memory")
#define BAR2_ARRIVE() asm volatile("bar.arrive 2, 224;" ::: "memory")
#define BAR2_SYNC()   asm volatile("bar.sync   2, 224;" ::: "memory")
#define BAR3_SYNC()   asm volatile("bar.sync   3, 64;"  ::: "memory")

// ------------------------------ Threefry-2x32-20 ----------------------------
__device__ __forceinline__ uint32_t rotl32(uint32_t x, int r){ return (x << r) | (x >> (32 - r)); }
__device__ __forceinline__ float tf_uniform(uint32_t flat){
    // JAX partitionable threefry, key (0,42): bits = out0 ^ out1
    uint32_t k0 = 0u, k1 = 42u, ks2 = k0 ^ k1 ^ 0x1BD11BDAu;
    uint32_t x0 = 0u + k0, x1 = flat + k1;
#define TF_R(r) { x0 += x1; x1 = rotl32(x1, (r)); x1 ^= x0; }
    TF_R(13) TF_R(15) TF_R(26) TF_R(6)   x0 += k1;  x1 += ks2 + 1u;
    TF_R(17) TF_R(29) TF_R(16) TF_R(24)  x0 += ks2; x1 += k0  + 2u;
    TF_R(13) TF_R(15) TF_R(26) TF_R(6)   x0 += k0;  x1 += k1  + 3u;
    TF_R(17) TF_R(29) TF_R(16) TF_R(24)  x0 += k1;  x1 += ks2 + 4u;
    TF_R(13) TF_R(15) TF_R(26) TF_R(6)   x0 += ks2; x1 += k0  + 5u;
#undef TF_R
    uint32_t bits = x0 ^ x1;
    return __uint_as_float((bits >> 9) | 0x3F800000u) - 1.0f;
}

// 64-term packed-f32x2 column dot (2 accumulators)
__device__ __forceinline__ float col_dot(const float* sh, const unsigned long long* w2,
                                         float base)
{
    unsigned long long a0 = 0ull, a1 = 0ull;
    const ulonglong2* h2 = reinterpret_cast<const ulonglong2*>(sh);
#pragma unroll
    for (int q = 0; q < 8; q++) {
        ulonglong2 u = h2[q], v = h2[q + 8];
        fma2(a0, w2[2*q],      u.x);
        fma2(a1, w2[2*q + 1],  u.y);
        fma2(a0, w2[2*q + 16], v.x);
        fma2(a1, w2[2*q + 17], v.y);
    }
    add2(a0, a1);
    float2 r = unpack2(a0);
    return (r.x + r.y) + base;
}

// --------------------------- shared memory union -----------------------------
union SmemU {
    struct {
        float h[HID];
        float v[384];
        float dt[LP1];
    } scan;
    struct {
        float4 stg[7][HID];
        float  red[7];
    } mc;
};

// ------------------------------- main kernel ---------------------------------
__global__ void __launch_bounds__(NTHR, 1)
hawkes_kernel(const float* __restrict__ seq,    // [B, L, 1]
              const float* __restrict__ Wrec,   // [65, 448]
              const float* __restrict__ brec,   // [448]
              const float* __restrict__ Wf,     // [64]
              const float* __restrict__ bf,     // [1]
              const int*   __restrict__ lens,   // [B]
              float*       __restrict__ out)
{
    __shared__ SmemU smem;

    const int j    = threadIdx.x;
    const int w    = j >> 5;
    const int lane = j & 31;

    if (blockIdx.x < BATCH) {
        // ========================= SCAN role ===============================
        const int b   = blockIdx.x;
        const int len = lens[b];
        const float* sp = seq + b * MAXL;
        float* s_h  = smem.scan.h;
        float* s_v  = smem.scan.v;
        float* s_dt = smem.scan.dt;

        for (int l = j; l <= MAXL; l += NTHR) {
            float v;
            if (l < len)        v = (l == 0) ? sp[0] : sp[l] - sp[l - 1];
            else if (l == len)  v = T_END - sp[len - 1];
            else                v = -1.0f;
            s_dt[l] = v;
        }

        const int c0 = j;               // first column
        const int c1 = j + NTHR;        // second column
        const bool epi = (j >= 160);    // c1 in gate 6 -> epilogue thread
        const int ch  = j - 160;        // epilogue channel

        if (epi) {
            s_h[ch] = 0.0f;
            g_state[(b * LP1) * HID + ch] = make_float4(0.f, 0.f, 0.f, 0.f);
        }

        // weights for both columns
        const float w00 = Wrec[c0], bj0 = brec[c0];
        const float w01 = Wrec[c1], bj1 = brec[c1];
        unsigned long long w2a[32], w2b[32];
#pragma unroll
        for (int k = 0; k < 32; k++) {
            w2a[k] = pack2(Wrec[(2*k + 1) * NCOL + c0], Wrec[(2*k + 2) * NCOL + c0]);
            w2b[k] = pack2(Wrec[(2*k + 1) * NCOL + c1], Wrec[(2*k + 2) * NCOL + c1]);
        }

        // branchless nonlinearity constants (FIXED: ga = 0.5 for sigmoid)
        const int g0 = c0 >> 6, g1 = c1 >> 6;
        const float al0 = (g0 == 2) ? 1.0f : 0.5f, be0 = al0;
        const float ga0 = (g0 == 2) ? 0.0f : 0.5f;
        const float al1 = (g1 == 2) ? 1.0f : 0.5f, be1 = al1;
        const float ga1 = (g1 == 2) ? 0.0f : 0.5f;

        __syncthreads();

        if (!epi) {
            // ----- producers: warps 0-4, two gate columns per thread -----
            for (int l = 0; l < len; l++) {
                const float dt = s_dt[l];
                const float acc0 = col_dot(s_h, w2a, fmaf(w00, dt, bj0));
                const float acc1 = col_dot(s_h, w2b, fmaf(w01, dt, bj1));
                s_v[c0] = fmaf(al0, tanh_mufu(be0 * acc0), ga0);
                s_v[c1] = fmaf(al1, tanh_mufu(be1 * acc1), ga1);
                BAR1_ARRIVE();
                BAR2_SYNC();            // h(l+1) ready
            }
        } else {
            // ----- epilogue: warps 5-6 (c1 = gate-6 column of channel ch) --
            float ct = 0.0f, cbar = 0.0f;
            for (int l = 0; l < len; l++) {
                const float dt = s_dt[l];
                const float acc0 = col_dot(s_h, w2a, fmaf(w00, dt, bj0));
                const float acc1 = col_dot(s_h, w2b, fmaf(w01, dt, bj1));
                s_v[c0] = fmaf(al0, tanh_mufu(be0 * acc0), ga0);
                const float dec = fsoftplus(acc1);
                const float e   = ex2f(-dec * s_dt[l + 1] * LOG2E);

                BAR1_SYNC();            // gates ready
                const float iG = s_v[ch],        fG = s_v[ 64 + ch];
                const float zG = s_v[128 + ch],  oG = s_v[192 + ch];
                const float ib = s_v[256 + ch],  fb = s_v[320 + ch];
                const float c  = fmaf(fG, ct, iG * zG);
                const float cb = fmaf(fb, cbar, ib * zG);
                const float cd = fmaf(c - cb, e, cb);
                const float bef = oG * tanh_mufu(cd);
                ct = cd; cbar = cb;
                s_h[ch] = bef;
                BAR2_ARRIVE();          // release producers immediately

                g_state[(b * LP1 + l + 1) * HID + ch] = make_float4(c, cb, oG, dec);
                BAR3_SYNC();            // orders ALL epi STGs (sites <= l+1)
                if (ch == 0 && ((l + 1) & 63) == 0)
                    st_release_u32(&g_flag[b], (unsigned)((l + 1) >> 6));
            }
            if (ch == 0)
                st_release_u32(&g_flag[b], 1u << 20);
        }
    } else {
        // ===================== MC CONSUMER role (7 warps) ==================
        const int b   = blockIdx.x - BATCH;
        const int len = lens[b];
        const float bfv = bf[0];
        const float* sp = seq + b * MAXL;
        const float wf0 = Wf[lane], wf1 = Wf[lane + 32];
        float4* stg = smem.mc.stg[w];

        float acc = 0.0f;               // lane 0 per warp

        for (int k = 0; 64 * k <= len; k++) {
            if (j == 0) {
                while (ld_acquire_u32(&g_flag[b]) < (unsigned)(k + 1))
                    __nanosleep(256);
            }
            __syncthreads();

            const int sLim = min(64 * k + 63, len);
            for (int s = 64 * k + w; s <= sLim; s += 7) {
                float dtl;
                if (s < len) dtl = (s == 0) ? sp[0] : sp[s] - sp[s - 1];
                else         dtl = T_END - sp[len - 1];

                const int base = (b * LP1 + s) * HID;
                const float4 s0 = g_state[base + lane];
                const float4 s1 = g_state[base + lane + 32];
                const float mscale = -dtl * LOG2E;
                stg[lane]      = make_float4(s0.w * mscale, s0.x - s0.y, s0.y, s0.z * wf0);
                stg[lane + 32] = make_float4(s1.w * mscale, s1.x - s1.y, s1.y, s1.z * wf1);
                __syncwarp();

                float u = 1.0f;         // lanes 30,31: u=1 (lane30 dot = before.Wf)
                if (lane < NMC)
                    u = tf_uniform((uint32_t)lane * (uint32_t)TOTAL
                                   + (uint32_t)(b * LP1 + s));
                float a0 = 0.0f, a1 = 0.0f;
#pragma unroll 8
                for (int ch = 0; ch < HID; ch += 2) {
                    const float4 t0 = stg[ch], t1 = stg[ch + 1];
                    a0 = fmaf(t0.w, tanh_mufu(fmaf(t0.y, ex2f(u * t0.x), t0.z)), a0);
                    a1 = fmaf(t1.w, tanh_mufu(fmaf(t1.y, ex2f(u * t1.x), t1.z)), a1);
                }
                const float dot = a0 + a1;

                float spv = (lane < NMC) ? fsoftplus(dot + bfv) : 0.0f;
#pragma unroll
                for (int off = 16; off; off >>= 1)
                    spv += __shfl_xor_sync(0xFFFFFFFFu, spv, off);
                const float q = __shfl_sync(0xFFFFFFFFu, dot, 30);

                if (lane == 0) {
                    const float lamb_int = (spv * (1.0f / NMC) + EPS_L) * dtl;
                    float ev = 0.0f;
                    if (s < len) ev = flog(fsoftplus(q + bfv) + EPS_L);
                    acc += ev - lamb_int;
                }
                __syncwarp();
            }
        }

        if (lane == 0) smem.mc.red[w] = acc;
        __syncthreads();
        if (j == 0) {
            float S = 0.0f;
#pragma unroll
            for (int k = 0; k < 7; k++) S += smem.mc.red[k];
            g_part[b] = S;
            __threadfence();
            if (atomicAdd(&g_done, 1u) == (unsigned)(BATCH - 1)) {
                float T = 0.0f;
#pragma unroll 8
                for (int k = 0; k < BATCH; k++) T += g_part[k];
                out[0] = -T * (1.0f / BATCH);
                for (int k = 0; k < BATCH; k++) g_flag[k] = 0u;
                g_done = 0u;
            }
        }
    }
}

// ------------------------------- launcher ------------------------------------
extern "C" void kernel_launch(void* const* d_in, const int* in_sizes, int n_in,
                              void* d_out, int out_size)
{
    const float* seq  = nullptr;
    const float* Wrec = nullptr;
    const float* brec = nullptr;
    const float* Wf   = nullptr;
    const float* bf   = nullptr;
    const int*   lens = nullptr;
    for (int i = 0; i < n_in; i++) {
        const int s = in_sizes[i];
        if      (s == BATCH * MAXL)     seq  = (const float*)d_in[i];
        else if (s == 65 * NCOL)        Wrec = (const float*)d_in[i];
        else if (s == NCOL)             brec = (const float*)d_in[i];
        else if (s == 1)                bf   = (const float*)d_in[i];
        else if (s == HID) {
            if (!Wf) Wf = (const float*)d_in[i];
            else     lens = (const int*)d_in[i];
        }
    }

    hawkes_kernel<<<2 * BATCH, NTHR>>>(seq, Wrec, brec, Wf, bf, lens, (float*)d_out);
}